// round 11
// baseline (speedup 1.0000x reference)
#include <cuda_runtime.h>
#include <cuda_bf16.h>
#include <math.h>
#include <stdint.h>

// Problem constants
#define Bv   2
#define Tv   2048
#define Dm   1024
#define NH   16
#define NKV  4
#define HD   64
#define WIN  128
#define Mtok (Bv*Tv)        // 4096
#define DFF  (4*Dm)         // 4096
#define NQKV 1536           // 1024 Q + 256 K + 256 V

// ---------------- scratch (device globals) ---------------------------------
__device__ __align__(256) __nv_bfloat16 g_Xhi[Mtok*Dm],  g_Xlo[Mtok*Dm];
__device__ __align__(256) __nv_bfloat16 g_Wqkv_hi[NQKV*Dm], g_Wqkv_lo[NQKV*Dm];
__device__ __align__(256) __nv_bfloat16 g_W1hi[(size_t)DFF*Dm], g_W1lo[(size_t)DFF*Dm];
__device__ __align__(256) __nv_bfloat16 g_W2hi[(size_t)Dm*DFF], g_W2lo[(size_t)Dm*DFF];
__device__ __align__(256) __nv_bfloat16 g_AOhi[Mtok*Dm], g_AOlo[Mtok*Dm];
__device__ __align__(256) __nv_bfloat16 g_H1hi[(size_t)Mtok*DFF], g_H1lo[(size_t)Mtok*DFF];
__device__ __align__(256) float g_Q[(size_t)Bv*NH*Tv*HD];
__device__ __align__(256) float g_K[(size_t)Bv*NKV*Tv*HD];
__device__ __align__(256) float g_V[(size_t)Bv*NKV*Tv*HD];
__device__ float g_cosT[Tv*32], g_sinT[Tv*32];

// ---------------- helpers ---------------------------------------------------
__device__ __forceinline__ uint32_t smem_u32(const void* p) {
    uint32_t a;
    asm("{ .reg .u64 t; cvta.to.shared.u64 t, %1; cvt.u32.u64 %0, t; }" : "=r"(a) : "l"(p));
    return a;
}
#define LDMX4(r0,r1,r2,r3,addr) \
    asm volatile("ldmatrix.sync.aligned.m8n8.x4.shared.b16 {%0,%1,%2,%3}, [%4];" \
        : "=r"(r0), "=r"(r1), "=r"(r2), "=r"(r3) : "r"(addr))
#define MMA16816(d, a, b) \
    asm volatile("mma.sync.aligned.m16n8k16.row.col.f32.bf16.bf16.f32 " \
        "{%0,%1,%2,%3}, {%4,%5,%6,%7}, {%8,%9}, {%0,%1,%2,%3};" \
        : "+f"((d)[0]), "+f"((d)[1]), "+f"((d)[2]), "+f"((d)[3]) \
        : "r"((a)[0]), "r"((a)[1]), "r"((a)[2]), "r"((a)[3]), "r"((b)[0]), "r"((b)[1]))

// ---------------- warp-MMA bf16-split GEMM ----------------------------------
// C[M,N] = A[M,K] @ B[N,K]^T with A = Ahi+Alo, B = Bhi+Blo (bf16 pairs),
// computed as Ahi@Bhi + Ahi@Blo + Alo@Bhi, fp32 register accumulators.
// EPI 0: fp32 C.  EPI 1: SiLU -> bf16 hi/lo split.  EPI 2: RoPE+permute QKV.
#define GBM 128
#define GBN 128
#define GBK 32
#define KP  40                      // padded row length (bf16) -> 80B stride
#define TILEB (128*KP*2)            // 10240 B per tile
#define STAGE (4*TILEB)             // Ahi,Alo,Bhi,Blo
#define GEMM_SMEM (2*STAGE)         // 81920 B (also >= 128*132*4 for EPI2)

template<int EPI>
__global__ __launch_bounds__(256,2)
void mma_gemm(const __nv_bfloat16* __restrict__ Ahi, const __nv_bfloat16* __restrict__ Alo,
              const __nv_bfloat16* __restrict__ Bhi, const __nv_bfloat16* __restrict__ Blo,
              float* __restrict__ Cf,
              __nv_bfloat16* __restrict__ Chi, __nv_bfloat16* __restrict__ Clo,
              float* __restrict__ Qo, float* __restrict__ Ko, float* __restrict__ Vo,
              int M, int N, int K)
{
    extern __shared__ char dsm[];
    const uint32_t sbase = smem_u32(dsm);
    const int tid   = threadIdx.x;
    const int lane  = tid & 31;
    const int wid   = tid >> 5;
    const int warpM = wid & 1;          // 2 x 64 rows
    const int warpN = wid >> 1;         // 4 x 32 cols
    const int bm    = blockIdx.y * GBM;
    const int bn    = blockIdx.x * GBN;

    const __nv_bfloat16* gp[4] = {Ahi, Alo, Bhi, Blo};

    auto load_stage = [&](int chunk, int buf) {
        const uint32_t st = sbase + buf * STAGE;
        const int k0 = chunk * GBK;
        #pragma unroll
        for (int i = 0; i < 8; i++) {
            int c   = i * 256 + tid;
            int t4  = c >> 9;
            int r   = (c >> 2) & 127;
            int s   = c & 3;
            int grow = (t4 < 2 ? bm : bn) + r;
            const char* src = (const char*)(gp[t4] + (size_t)grow * K + k0 + s * 8);
            uint32_t dst = st + t4 * TILEB + r * (KP * 2) + s * 16;
            asm volatile("cp.async.cg.shared.global [%0], [%1], 16;" :: "r"(dst), "l"(src));
        }
        asm volatile("cp.async.commit_group;" ::: "memory");
    };

    float acc[4][4][4];
    #pragma unroll
    for (int i = 0; i < 4; i++)
        #pragma unroll
        for (int j = 0; j < 4; j++)
            #pragma unroll
            for (int q = 0; q < 4; q++) acc[i][j][q] = 0.f;

    const int arow = (lane & 7) + 8 * ((lane >> 3) & 1);
    const int acol = 8 * (lane >> 4);
    const int brow = (lane & 7) + 8 * (lane >> 4);
    const int bcol = 8 * ((lane >> 3) & 1);

    const int C = K / GBK;
    load_stage(0, 0);

    for (int c = 0; c < C; c++) {
        const int buf = c & 1;
        if (c + 1 < C) {
            load_stage(c + 1, buf ^ 1);
            asm volatile("cp.async.wait_group 1;" ::: "memory");
        } else {
            asm volatile("cp.async.wait_group 0;" ::: "memory");
        }
        __syncthreads();

        const uint32_t sAh = sbase + buf * STAGE;
        const uint32_t sAl = sAh + TILEB;
        const uint32_t sBh = sAh + 2 * TILEB;
        const uint32_t sBl = sAh + 3 * TILEB;

        #pragma unroll
        for (int ks = 0; ks < 2; ks++) {
            const int kb = ks * 16;
            uint32_t a[4][4], bh[4][2], bl[4][2];

            #pragma unroll
            for (int mf = 0; mf < 4; mf++) {
                uint32_t ad = sAh + (((warpM * 64 + mf * 16 + arow) * KP) + kb + acol) * 2;
                LDMX4(a[mf][0], a[mf][1], a[mf][2], a[mf][3], ad);
            }
            #pragma unroll
            for (int nf2 = 0; nf2 < 2; nf2++) {
                uint32_t bd = sBh + (((warpN * 32 + nf2 * 16 + brow) * KP) + kb + bcol) * 2;
                LDMX4(bh[nf2*2][0], bh[nf2*2][1], bh[nf2*2+1][0], bh[nf2*2+1][1], bd);
            }
            #pragma unroll
            for (int mf = 0; mf < 4; mf++)
                #pragma unroll
                for (int nf = 0; nf < 4; nf++)
                    MMA16816(acc[mf][nf], a[mf], bh[nf]);       // hi x hi

            #pragma unroll
            for (int nf2 = 0; nf2 < 2; nf2++) {
                uint32_t bd = sBl + (((warpN * 32 + nf2 * 16 + brow) * KP) + kb + bcol) * 2;
                LDMX4(bl[nf2*2][0], bl[nf2*2][1], bl[nf2*2+1][0], bl[nf2*2+1][1], bd);
            }
            #pragma unroll
            for (int mf = 0; mf < 4; mf++)
                #pragma unroll
                for (int nf = 0; nf < 4; nf++)
                    MMA16816(acc[mf][nf], a[mf], bl[nf]);       // hi x lo

            #pragma unroll
            for (int mf = 0; mf < 4; mf++) {
                uint32_t ad = sAl + (((warpM * 64 + mf * 16 + arow) * KP) + kb + acol) * 2;
                LDMX4(a[mf][0], a[mf][1], a[mf][2], a[mf][3], ad);
            }
            #pragma unroll
            for (int mf = 0; mf < 4; mf++)
                #pragma unroll
                for (int nf = 0; nf < 4; nf++)
                    MMA16816(acc[mf][nf], a[mf], bh[nf]);       // lo x hi
        }
        __syncthreads();
    }

    const int g = lane >> 2, i4 = lane & 3;

    if (EPI == 2) {
        // stage fp32 tile to smem (pipeline buffers are drained)
        float* st = (float*)dsm;            // [128][132]
        #pragma unroll
        for (int mf = 0; mf < 4; mf++)
            #pragma unroll
            for (int nf = 0; nf < 4; nf++) {
                int r0 = warpM * 64 + mf * 16 + g;
                int cc = warpN * 32 + nf * 8 + 2 * i4;
                st[r0 * 132 + cc]       = acc[mf][nf][0];
                st[r0 * 132 + cc + 1]   = acc[mf][nf][1];
                st[(r0+8) * 132 + cc]   = acc[mf][nf][2];
                st[(r0+8) * 132 + cc+1] = acc[mf][nf][3];
            }
        __syncthreads();
        // rope + scatter: 128 rows x 2 head-cols x 32 dd = 8192 items
        #pragma unroll 4
        for (int it = 0; it < 32; it++) {
            int idx  = it * 256 + tid;
            int r    = idx >> 6;
            int rest = idx & 63;
            int hcol = rest >> 5;
            int dd   = rest & 31;
            int tok  = bm + r;
            int t    = tok & (Tv - 1);
            int b    = tok >> 11;
            int gc   = bn + hcol * 64;
            float s1 = st[r * 132 + hcol * 64 + dd];
            float s2 = st[r * 132 + hcol * 64 + dd + 32];
            float* dst;
            bool rot = true;
            if (gc < 1024)       dst = Qo + ((size_t)(b * NH  + (gc >> 6)) * Tv + t) * HD;
            else if (gc < 1280)  dst = Ko + ((size_t)(b * NKV + ((gc - 1024) >> 6)) * Tv + t) * HD;
            else               { dst = Vo + ((size_t)(b * NKV + ((gc - 1280) >> 6)) * Tv + t) * HD; rot = false; }
            float o1 = s1, o2 = s2;
            if (rot) {
                float cs = g_cosT[t * 32 + dd], sn = g_sinT[t * 32 + dd];
                o1 = s1 * cs - s2 * sn;
                o2 = s1 * sn + s2 * cs;
            }
            dst[dd]      = o1;
            dst[dd + 32] = o2;
        }
        return;
    }

    #pragma unroll
    for (int mf = 0; mf < 4; mf++) {
        #pragma unroll
        for (int nf = 0; nf < 4; nf++) {
            int row0 = bm + warpM * 64 + mf * 16 + g;
            int col  = bn + warpN * 32 + nf * 8 + 2 * i4;
            float d0 = acc[mf][nf][0], d1 = acc[mf][nf][1];
            float d2 = acc[mf][nf][2], d3 = acc[mf][nf][3];
            if (EPI == 0) {
                *(float2*)&Cf[(size_t)row0 * N + col]       = make_float2(d0, d1);
                *(float2*)&Cf[(size_t)(row0 + 8) * N + col] = make_float2(d2, d3);
            } else {
                float a0 = d0 / (1.f + __expf(-d0));
                float a1 = d1 / (1.f + __expf(-d1));
                float a2 = d2 / (1.f + __expf(-d2));
                float a3 = d3 / (1.f + __expf(-d3));
                __nv_bfloat16 h0 = __float2bfloat16(a0), h1 = __float2bfloat16(a1);
                __nv_bfloat16 h2 = __float2bfloat16(a2), h3 = __float2bfloat16(a3);
                __nv_bfloat16 l0 = __float2bfloat16(a0 - __bfloat162float(h0));
                __nv_bfloat16 l1 = __float2bfloat16(a1 - __bfloat162float(h1));
                __nv_bfloat16 l2 = __float2bfloat16(a2 - __bfloat162float(h2));
                __nv_bfloat16 l3 = __float2bfloat16(a3 - __bfloat162float(h3));
                *(__nv_bfloat162*)&Chi[(size_t)row0 * N + col]       = __halves2bfloat162(h0, h1);
                *(__nv_bfloat162*)&Chi[(size_t)(row0 + 8) * N + col] = __halves2bfloat162(h2, h3);
                *(__nv_bfloat162*)&Clo[(size_t)row0 * N + col]       = __halves2bfloat162(l0, l1);
                *(__nv_bfloat162*)&Clo[(size_t)(row0 + 8) * N + col] = __halves2bfloat162(l2, l3);
            }
        }
    }
}

// ---------------- fp32 -> bf16 hi/lo split ---------------------------------
__global__ void split_kernel(const float* __restrict__ in,
                             __nv_bfloat16* __restrict__ hi,
                             __nv_bfloat16* __restrict__ lo, int n)
{
    int i = blockIdx.x * 256 + threadIdx.x;
    if (i * 4 >= n) return;
    float4 v = ((const float4*)in)[i];
    __nv_bfloat16 h0 = __float2bfloat16(v.x), h1 = __float2bfloat16(v.y);
    __nv_bfloat16 h2 = __float2bfloat16(v.z), h3 = __float2bfloat16(v.w);
    __nv_bfloat16 l0 = __float2bfloat16(v.x - __bfloat162float(h0));
    __nv_bfloat16 l1 = __float2bfloat16(v.y - __bfloat162float(h1));
    __nv_bfloat16 l2 = __float2bfloat16(v.z - __bfloat162float(h2));
    __nv_bfloat16 l3 = __float2bfloat16(v.w - __bfloat162float(h3));
    ((__nv_bfloat162*)hi)[2*i]   = __halves2bfloat162(h0, h1);
    ((__nv_bfloat162*)hi)[2*i+1] = __halves2bfloat162(h2, h3);
    ((__nv_bfloat162*)lo)[2*i]   = __halves2bfloat162(l0, l1);
    ((__nv_bfloat162*)lo)[2*i+1] = __halves2bfloat162(l2, l3);
}

// ---------------- RoPE table ------------------------------------------------
__global__ void rope_table_kernel()
{
    int idx = blockIdx.x * 256 + threadIdx.x;
    if (idx >= Tv * 32) return;
    int t = idx >> 5, d = idx & 31;
    double invf = pow(10000.0, -(double)d / 32.0);
    double ang  = fmod((double)t * invf, 6.283185307179586476925287);
    g_cosT[idx] = (float)cos(ang);
    g_sinT[idx] = (float)sin(ang);
}

// ---------------- sliding-window GQA attention (2 heads per block) ---------
#define QB   8
#define NR   (WIN + QB - 1)    // 135
#define KSTR 68
#define ATTN_SMEM ((NR*KSTR + NR*HD + 2*QB*HD) * (int)sizeof(float))

__global__ __launch_bounds__(512) void attn_kernel(const float* __restrict__ Q,
                                                   const float* __restrict__ K,
                                                   const float* __restrict__ V,
                                                   __nv_bfloat16* __restrict__ Ohi,
                                                   __nv_bfloat16* __restrict__ Olo)
{
    extern __shared__ float smem[];
    float* Ks = smem;                    // [NR][KSTR]
    float* Vs = Ks + NR * KSTR;          // [NR][64]
    float* Qs = Vs + NR * HD;            // [2][QB][64]

    const int b    = blockIdx.z;
    const int kvh  = blockIdx.y >> 1;
    const int hp   = blockIdx.y & 1;
    const int h0   = kvh * 4 + hp * 2;   // this block: heads h0, h0+1
    const int qs   = blockIdx.x * QB;
    const int tid  = threadIdx.x;
    const int lane = tid & 31;
    const int wid  = tid >> 5;           // 16 warps
    const int hh   = wid >> 3;           // head within pair
    const int wr   = wid & 7;            // query row

    const int kbase = qs - (WIN - 1);
    const float* Kg = K + (size_t)(b * NKV + kvh) * Tv * HD;
    const float* Vg = V + (size_t)(b * NKV + kvh) * Tv * HD;

    for (int idx = tid; idx < NR * HD; idx += 512) {
        int j = idx >> 6, d = idx & 63;
        int kidx = kbase + j;
        float kv = 0.f, vv = 0.f;
        if (kidx >= 0) {
            kv = Kg[(size_t)kidx * HD + d];
            vv = Vg[(size_t)kidx * HD + d];
        }
        Ks[j * KSTR + d] = kv;
        Vs[j * HD   + d] = vv;
    }
    for (int idx = tid; idx < 2 * QB * HD; idx += 512) {
        int hl = idx >> 9, r = (idx >> 6) & 7, d = idx & 63;
        Qs[idx] = Q[((size_t)(b * NH + h0 + hl) * Tv + (qs + r)) * HD + d];
    }
    __syncthreads();

    const int qi = qs + wr;
    const int h  = h0 + hh;
    float4 qreg[16];
    const float4* q4 = (const float4*)(Qs + (hh * QB + wr) * HD);
    #pragma unroll
    for (int i = 0; i < 16; i++) qreg[i] = q4[i];

    float sc[4];
    #pragma unroll
    for (int c = 0; c < 4; c++) {
        int l = lane + 32 * c;
        int kidx = qi - (WIN - 1) + l;
        if (kidx >= 0) {
            const float4* k4 = (const float4*)(Ks + (wr + l) * KSTR);
            float acc = 0.f;
            #pragma unroll
            for (int i = 0; i < 16; i++) {
                float4 kk = k4[i];
                acc += qreg[i].x*kk.x + qreg[i].y*kk.y + qreg[i].z*kk.z + qreg[i].w*kk.w;
            }
            sc[c] = acc * 0.125f;
        } else {
            sc[c] = -INFINITY;
        }
    }

    float m = fmaxf(fmaxf(sc[0], sc[1]), fmaxf(sc[2], sc[3]));
    #pragma unroll
    for (int off = 16; off >= 1; off >>= 1)
        m = fmaxf(m, __shfl_xor_sync(0xffffffffu, m, off));
    float p[4]; float sum = 0.f;
    #pragma unroll
    for (int c = 0; c < 4; c++) { p[c] = __expf(sc[c] - m); sum += p[c]; }
    #pragma unroll
    for (int off = 16; off >= 1; off >>= 1)
        sum += __shfl_xor_sync(0xffffffffu, sum, off);
    const float inv = 1.f / sum;
    #pragma unroll
    for (int c = 0; c < 4; c++) p[c] *= inv;

    float o0 = 0.f, o1 = 0.f;
    #pragma unroll 4
    for (int l = 0; l < WIN; l++) {
        float w = __shfl_sync(0xffffffffu, p[l >> 5], l & 31);
        const float* vrow = Vs + (wr + l) * HD;
        o0 = fmaf(w, vrow[lane],      o0);
        o1 = fmaf(w, vrow[lane + 32], o1);
    }
    // write bf16 hi/lo split directly (input to MLP1)
    const size_t obase = (size_t)(b * Tv + qi) * Dm + h * HD;
    __nv_bfloat16 hh0 = __float2bfloat16(o0), hh1 = __float2bfloat16(o1);
    Ohi[obase + lane]      = hh0;
    Ohi[obase + lane + 32] = hh1;
    Olo[obase + lane]      = __float2bfloat16(o0 - __bfloat162float(hh0));
    Olo[obase + lane + 32] = __float2bfloat16(o1 - __bfloat162float(hh1));
}

// ---------------- launch ----------------------------------------------------
extern "C" void kernel_launch(void* const* d_in, const int* in_sizes, int n_in,
                              void* d_out, int out_size)
{
    const float* X  = (const float*)d_in[0];
    const float* Wq = (const float*)d_in[1];
    const float* Wk = (const float*)d_in[2];
    const float* Wv = (const float*)d_in[3];
    const float* W1 = (const float*)d_in[4];
    const float* W2 = (const float*)d_in[5];
    float* out = (float*)d_out;

    __nv_bfloat16 *Xhi,*Xlo,*Wqkvhi,*Wqkvlo,*W1hi,*W1lo,*W2hi,*W2lo,*AOhi,*AOlo,*H1hi,*H1lo;
    float *Qh,*Kh,*Vh;
    cudaGetSymbolAddress((void**)&Xhi, g_Xhi);       cudaGetSymbolAddress((void**)&Xlo, g_Xlo);
    cudaGetSymbolAddress((void**)&Wqkvhi, g_Wqkv_hi);cudaGetSymbolAddress((void**)&Wqkvlo, g_Wqkv_lo);
    cudaGetSymbolAddress((void**)&W1hi, g_W1hi);     cudaGetSymbolAddress((void**)&W1lo, g_W1lo);
    cudaGetSymbolAddress((void**)&W2hi, g_W2hi);     cudaGetSymbolAddress((void**)&W2lo, g_W2lo);
    cudaGetSymbolAddress((void**)&AOhi, g_AOhi);     cudaGetSymbolAddress((void**)&AOlo, g_AOlo);
    cudaGetSymbolAddress((void**)&H1hi, g_H1hi);     cudaGetSymbolAddress((void**)&H1lo, g_H1lo);
    cudaGetSymbolAddress((void**)&Qh, g_Q);          cudaGetSymbolAddress((void**)&Kh, g_K);
    cudaGetSymbolAddress((void**)&Vh, g_V);

    cudaFuncSetAttribute(mma_gemm<0>, cudaFuncAttributeMaxDynamicSharedMemorySize, GEMM_SMEM);
    cudaFuncSetAttribute(mma_gemm<1>, cudaFuncAttributeMaxDynamicSharedMemorySize, GEMM_SMEM);
    cudaFuncSetAttribute(mma_gemm<2>, cudaFuncAttributeMaxDynamicSharedMemorySize, GEMM_SMEM);
    cudaFuncSetAttribute(attn_kernel, cudaFuncAttributeMaxDynamicSharedMemorySize, ATTN_SMEM);

    // 0) RoPE table (double-precision accurate, tiny)
    rope_table_kernel<<<(Tv*32 + 255)/256, 256>>>();

    // 1) bf16 hi/lo splits of input activations and weights
    split_kernel<<<(Mtok*Dm/4 + 255)/256, 256>>>(X,  Xhi, Xlo, Mtok*Dm);
    split_kernel<<<(Dm*Dm/4 + 255)/256, 256>>>(Wq, Wqkvhi,             Wqkvlo,             Dm*Dm);
    split_kernel<<<(NKV*HD*Dm/4 + 255)/256, 256>>>(Wk, Wqkvhi + 1024*Dm, Wqkvlo + 1024*Dm, NKV*HD*Dm);
    split_kernel<<<(NKV*HD*Dm/4 + 255)/256, 256>>>(Wv, Wqkvhi + 1280*Dm, Wqkvlo + 1280*Dm, NKV*HD*Dm);
    split_kernel<<<(DFF*Dm/4 + 255)/256, 256>>>(W1, W1hi, W1lo, DFF*Dm);
    split_kernel<<<(Dm*DFF/4 + 255)/256, 256>>>(W2, W2hi, W2lo, Dm*DFF);

    // 2) fused QKV projection + RoPE + head-permute (writes Qh/Kh/Vh directly)
    mma_gemm<2><<<dim3(NQKV/GBN, Mtok/GBM), 256, GEMM_SMEM>>>(
        Xhi, Xlo, Wqkvhi, Wqkvlo, nullptr, nullptr, nullptr, Qh, Kh, Vh, Mtok, NQKV, Dm);

    // 3) sliding-window attention (2 q-heads per block; writes bf16 split AO)
    attn_kernel<<<dim3(Tv/QB, 2*NKV, Bv), 512, ATTN_SMEM>>>(Qh, Kh, Vh, AOhi, AOlo);

    // 4) MLP1: H1 = silu(AO @ W1^T), written as bf16 hi/lo split
    mma_gemm<1><<<dim3(DFF/GBN, Mtok/GBM), 256, GEMM_SMEM>>>(
        AOhi, AOlo, W1hi, W1lo, nullptr, H1hi, H1lo, nullptr, nullptr, nullptr, Mtok, DFF, Dm);

    // 5) MLP2: out = H1 @ W2^T (fp32)
    mma_gemm<0><<<dim3(Dm/GBN, Mtok/GBM), 256, GEMM_SMEM>>>(
        H1hi, H1lo, W2hi, W2lo, out, nullptr, nullptr, nullptr, nullptr, nullptr, Mtok, Dm, DFF);
}

// round 12
// speedup vs baseline: 1.2769x; 1.2769x over previous
#include <cuda_runtime.h>
#include <cuda_fp16.h>
#include <math.h>
#include <stdint.h>

// Problem constants
#define Bv   2
#define Tv   2048
#define Dm   1024
#define NH   16
#define NKV  4
#define HD   64
#define WIN  128
#define Mtok (Bv*Tv)        // 4096
#define DFF  (4*Dm)         // 4096
#define NQKV 1536           // 1024 Q + 256 K + 256 V

// ---------------- scratch (device globals) ---------------------------------
__device__ __align__(256) __half g_Xhi[Mtok*Dm],  g_Xlo[Mtok*Dm];
__device__ __align__(256) __half g_Wqkv[NQKV*Dm];
__device__ __align__(256) __half g_W1[(size_t)DFF*Dm];
__device__ __align__(256) __half g_W2[(size_t)Dm*DFF];
__device__ __align__(256) __half g_AOhi[Mtok*Dm], g_AOlo[Mtok*Dm];
__device__ __align__(256) __half g_H1hi[(size_t)Mtok*DFF], g_H1lo[(size_t)Mtok*DFF];
__device__ __align__(256) float g_QKVlin[(size_t)Mtok*NQKV];
__device__ __align__(256) float g_Q[(size_t)Bv*NH*Tv*HD];
__device__ __align__(256) float g_K[(size_t)Bv*NKV*Tv*HD];
__device__ __align__(256) float g_V[(size_t)Bv*NKV*Tv*HD];
__device__ __align__(256) float g_AO[Mtok*Dm];
__device__ float g_cosT[Tv*32], g_sinT[Tv*32];

// ---------------- helpers ---------------------------------------------------
__device__ __forceinline__ uint32_t smem_u32(const void* p) {
    uint32_t a;
    asm("{ .reg .u64 t; cvta.to.shared.u64 t, %1; cvt.u32.u64 %0, t; }" : "=r"(a) : "l"(p));
    return a;
}
#define LDMX4(r0,r1,r2,r3,addr) \
    asm volatile("ldmatrix.sync.aligned.m8n8.x4.shared.b16 {%0,%1,%2,%3}, [%4];" \
        : "=r"(r0), "=r"(r1), "=r"(r2), "=r"(r3) : "r"(addr))
#define MMA16816(d, a, b) \
    asm volatile("mma.sync.aligned.m16n8k16.row.col.f32.f16.f16.f32 " \
        "{%0,%1,%2,%3}, {%4,%5,%6,%7}, {%8,%9}, {%0,%1,%2,%3};" \
        : "+f"((d)[0]), "+f"((d)[1]), "+f"((d)[2]), "+f"((d)[3]) \
        : "r"((a)[0]), "r"((a)[1]), "r"((a)[2]), "r"((a)[3]), "r"((b)[0]), "r"((b)[1]))

// ---------------- warp-MMA fp16 asymmetric-split GEMM -----------------------
// C[M,N] = A[M,K] @ B[N,K]^T with A = Ahi+Alo (fp16 pair), B = Bh (fp16).
// Two MMA passes: Ahi@Bh + Alo@Bh = A@Bh exactly (fp32 accumulate).
// Error = B's fp16 rounding only (~2^-11 relative, random-averaged over K).
// EPI 0: write fp32 Cf.  EPI 1: write SiLU(acc) split to fp16 Chi/Clo.
#define GBM 128
#define GBN 128
#define GBK 32
#define KP  40                      // padded row length (halves) -> 80B stride
#define TILEB (128*KP*2)            // 10240 B per tile
#define STAGE (3*TILEB)             // Ahi, Alo, Bh
#define GEMM_SMEM (2*STAGE)         // 61440 B

template<int EPI>
__global__ __launch_bounds__(256,2)
void mma_gemm(const __half* __restrict__ Ahi, const __half* __restrict__ Alo,
              const __half* __restrict__ Bh,
              float* __restrict__ Cf,
              __half* __restrict__ Chi, __half* __restrict__ Clo,
              int M, int N, int K)
{
    extern __shared__ char dsm[];
    const uint32_t sbase = smem_u32(dsm);
    const int tid   = threadIdx.x;
    const int lane  = tid & 31;
    const int wid   = tid >> 5;
    const int warpM = wid & 1;          // 2 x 64 rows
    const int warpN = wid >> 1;         // 4 x 32 cols
    const int bm    = blockIdx.y * GBM;
    const int bn    = blockIdx.x * GBN;

    const __half* gp[3] = {Ahi, Alo, Bh};

    // 1536 16B chunks per stage (3 tiles x 128 rows x 4 segs)
    auto load_stage = [&](int chunk, int buf) {
        const uint32_t st = sbase + buf * STAGE;
        const int k0 = chunk * GBK;
        #pragma unroll
        for (int i = 0; i < 6; i++) {
            int c   = i * 256 + tid;
            int t3  = c >> 9;
            int r   = (c >> 2) & 127;
            int s   = c & 3;
            int grow = (t3 < 2 ? bm : bn) + r;
            const char* src = (const char*)(gp[t3] + (size_t)grow * K + k0 + s * 8);
            uint32_t dst = st + t3 * TILEB + r * (KP * 2) + s * 16;
            asm volatile("cp.async.cg.shared.global [%0], [%1], 16;" :: "r"(dst), "l"(src));
        }
        asm volatile("cp.async.commit_group;" ::: "memory");
    };

    float acc[4][4][4];
    #pragma unroll
    for (int i = 0; i < 4; i++)
        #pragma unroll
        for (int j = 0; j < 4; j++)
            #pragma unroll
            for (int q = 0; q < 4; q++) acc[i][j][q] = 0.f;

    const int arow = (lane & 7) + 8 * ((lane >> 3) & 1);
    const int acol = 8 * (lane >> 4);
    const int brow = (lane & 7) + 8 * (lane >> 4);
    const int bcol = 8 * ((lane >> 3) & 1);

    const int C = K / GBK;
    load_stage(0, 0);

    for (int c = 0; c < C; c++) {
        const int buf = c & 1;
        if (c + 1 < C) {
            load_stage(c + 1, buf ^ 1);
            asm volatile("cp.async.wait_group 1;" ::: "memory");
        } else {
            asm volatile("cp.async.wait_group 0;" ::: "memory");
        }
        __syncthreads();

        const uint32_t sAh = sbase + buf * STAGE;
        const uint32_t sAl = sAh + TILEB;
        const uint32_t sBh = sAh + 2 * TILEB;

        #pragma unroll
        for (int ks = 0; ks < 2; ks++) {
            const int kb = ks * 16;
            uint32_t a[4][4], bh[4][2];

            #pragma unroll
            for (int nf2 = 0; nf2 < 2; nf2++) {
                uint32_t bd = sBh + (((warpN * 32 + nf2 * 16 + brow) * KP) + kb + bcol) * 2;
                LDMX4(bh[nf2*2][0], bh[nf2*2][1], bh[nf2*2+1][0], bh[nf2*2+1][1], bd);
            }
            #pragma unroll
            for (int mf = 0; mf < 4; mf++) {
                uint32_t ad = sAh + (((warpM * 64 + mf * 16 + arow) * KP) + kb + acol) * 2;
                LDMX4(a[mf][0], a[mf][1], a[mf][2], a[mf][3], ad);
            }
            #pragma unroll
            for (int mf = 0; mf < 4; mf++)
                #pragma unroll
                for (int nf = 0; nf < 4; nf++)
                    MMA16816(acc[mf][nf], a[mf], bh[nf]);       // hi_a x B

            #pragma unroll
            for (int mf = 0; mf < 4; mf++) {
                uint32_t ad = sAl + (((warpM * 64 + mf * 16 + arow) * KP) + kb + acol) * 2;
                LDMX4(a[mf][0], a[mf][1], a[mf][2], a[mf][3], ad);
            }
            #pragma unroll
            for (int mf = 0; mf < 4; mf++)
                #pragma unroll
                for (int nf = 0; nf < 4; nf++)
                    MMA16816(acc[mf][nf], a[mf], bh[nf]);       // lo_a x B
        }
        __syncthreads();
    }

    const int g = lane >> 2, i4 = lane & 3;
    #pragma unroll
    for (int mf = 0; mf < 4; mf++) {
        #pragma unroll
        for (int nf = 0; nf < 4; nf++) {
            int row0 = bm + warpM * 64 + mf * 16 + g;
            int col  = bn + warpN * 32 + nf * 8 + 2 * i4;
            float d0 = acc[mf][nf][0], d1 = acc[mf][nf][1];
            float d2 = acc[mf][nf][2], d3 = acc[mf][nf][3];
            if (EPI == 0) {
                *(float2*)&Cf[(size_t)row0 * N + col]       = make_float2(d0, d1);
                *(float2*)&Cf[(size_t)(row0 + 8) * N + col] = make_float2(d2, d3);
            } else {
                float a0 = d0 / (1.f + __expf(-d0));
                float a1 = d1 / (1.f + __expf(-d1));
                float a2 = d2 / (1.f + __expf(-d2));
                float a3 = d3 / (1.f + __expf(-d3));
                __half h0 = __float2half_rn(a0), h1 = __float2half_rn(a1);
                __half h2 = __float2half_rn(a2), h3 = __float2half_rn(a3);
                __half l0 = __float2half_rn(a0 - __half2float(h0));
                __half l1 = __float2half_rn(a1 - __half2float(h1));
                __half l2 = __float2half_rn(a2 - __half2float(h2));
                __half l3 = __float2half_rn(a3 - __half2float(h3));
                *(__half2*)&Chi[(size_t)row0 * N + col]       = __halves2half2(h0, h1);
                *(__half2*)&Chi[(size_t)(row0 + 8) * N + col] = __halves2half2(h2, h3);
                *(__half2*)&Clo[(size_t)row0 * N + col]       = __halves2half2(l0, l1);
                *(__half2*)&Clo[(size_t)(row0 + 8) * N + col] = __halves2half2(l2, l3);
            }
        }
    }
}

// ---------------- fp32 -> fp16 hi/lo split (A-side operands) ----------------
__global__ void split_kernel(const float* __restrict__ in,
                             __half* __restrict__ hi,
                             __half* __restrict__ lo, int n)
{
    int i = blockIdx.x * 256 + threadIdx.x;     // index of float4
    if (i * 4 >= n) return;
    float4 v = ((const float4*)in)[i];
    __half h0 = __float2half_rn(v.x), h1 = __float2half_rn(v.y);
    __half h2 = __float2half_rn(v.z), h3 = __float2half_rn(v.w);
    __half l0 = __float2half_rn(v.x - __half2float(h0));
    __half l1 = __float2half_rn(v.y - __half2float(h1));
    __half l2 = __float2half_rn(v.z - __half2float(h2));
    __half l3 = __float2half_rn(v.w - __half2float(h3));
    ((__half2*)hi)[2*i]   = __halves2half2(h0, h1);
    ((__half2*)hi)[2*i+1] = __halves2half2(h2, h3);
    ((__half2*)lo)[2*i]   = __halves2half2(l0, l1);
    ((__half2*)lo)[2*i+1] = __halves2half2(l2, l3);
}

// ---------------- fp32 -> fp16 convert (B-side weights, hi only) ------------
__global__ void cvt_kernel(const float* __restrict__ in, __half* __restrict__ out, int n)
{
    int i = blockIdx.x * 256 + threadIdx.x;
    if (i * 4 >= n) return;
    float4 v = ((const float4*)in)[i];
    ((__half2*)out)[2*i]   = __halves2half2(__float2half_rn(v.x), __float2half_rn(v.y));
    ((__half2*)out)[2*i+1] = __halves2half2(__float2half_rn(v.z), __float2half_rn(v.w));
}

// ---------------- RoPE table ------------------------------------------------
__global__ void rope_table_kernel()
{
    int idx = blockIdx.x * 256 + threadIdx.x;
    if (idx >= Tv * 32) return;
    int t = idx >> 5, d = idx & 31;
    double invf = pow(10000.0, -(double)d / 32.0);
    double ang  = fmod((double)t * invf, 6.283185307179586476925287);
    g_cosT[idx] = (float)cos(ang);
    g_sinT[idx] = (float)sin(ang);
}

// QKVlin [tok][1536] -> out [b][h][t][64], rotate pairs (d, d+32) if doRot
__global__ void rope_apply_kernel(const float* __restrict__ lin, float* __restrict__ out,
                                  int Hn, int colOff, int doRot)
{
    int idx = blockIdx.x * 256 + threadIdx.x;
    int total = Mtok * Hn * 32;
    if (idx >= total) return;
    int d   = idx & 31;
    int h   = (idx >> 5) % Hn;
    int tok = idx / (32 * Hn);
    int t   = tok % Tv;
    int b   = tok / Tv;
    const float* src = lin + (size_t)tok * NQKV + colOff + h * HD;
    float x1 = src[d], x2 = src[d + 32], o1 = x1, o2 = x2;
    if (doRot) {
        float c = g_cosT[t * 32 + d], s = g_sinT[t * 32 + d];
        o1 = x1 * c - x2 * s;
        o2 = x1 * s + x2 * c;
    }
    float* dst = out + ((size_t)(b * Hn + h) * Tv + t) * HD;
    dst[d]      = o1;
    dst[d + 32] = o2;
}

// ---------------- sliding-window GQA attention (R6 config, known-good) ------
#define QB   8
#define NR   (WIN + QB - 1)    // 135
#define KSTR 68
#define ATTN_SMEM ((NR*KSTR + NR*HD + QB*HD) * (int)sizeof(float))

__global__ __launch_bounds__(256) void attn_kernel(const float* __restrict__ Q,
                                                   const float* __restrict__ K,
                                                   const float* __restrict__ V,
                                                   float* __restrict__ O)
{
    extern __shared__ float smem[];
    float* Ks = smem;
    float* Vs = Ks + NR * KSTR;
    float* Qs = Vs + NR * HD;

    const int b   = blockIdx.z;
    const int h   = blockIdx.y;
    const int qs  = blockIdx.x * QB;
    const int kvh = h >> 2;
    const int tid  = threadIdx.x;
    const int lane = tid & 31;
    const int wr   = tid >> 5;

    const int kbase = qs - (WIN - 1);
    const float* Kg = K + (size_t)(b * NKV + kvh) * Tv * HD;
    const float* Vg = V + (size_t)(b * NKV + kvh) * Tv * HD;

    for (int idx = tid; idx < NR * HD; idx += 256) {
        int j = idx >> 6, d = idx & 63;
        int kidx = kbase + j;
        float kv = 0.f, vv = 0.f;
        if (kidx >= 0) {
            kv = Kg[(size_t)kidx * HD + d];
            vv = Vg[(size_t)kidx * HD + d];
        }
        Ks[j * KSTR + d] = kv;
        Vs[j * HD   + d] = vv;
    }
    for (int idx = tid; idx < QB * HD; idx += 256) {
        int r = idx >> 6, d = idx & 63;
        Qs[idx] = Q[((size_t)(b * NH + h) * Tv + (qs + r)) * HD + d];
    }
    __syncthreads();

    const int qi = qs + wr;
    float4 qreg[16];
    const float4* q4 = (const float4*)(Qs + wr * HD);
    #pragma unroll
    for (int i = 0; i < 16; i++) qreg[i] = q4[i];

    float sc[4];
    #pragma unroll
    for (int c = 0; c < 4; c++) {
        int l = lane + 32 * c;
        int kidx = qi - (WIN - 1) + l;
        if (kidx >= 0) {
            const float4* k4 = (const float4*)(Ks + (wr + l) * KSTR);
            float acc = 0.f;
            #pragma unroll
            for (int i = 0; i < 16; i++) {
                float4 kk = k4[i];
                acc += qreg[i].x*kk.x + qreg[i].y*kk.y + qreg[i].z*kk.z + qreg[i].w*kk.w;
            }
            sc[c] = acc * 0.125f;
        } else {
            sc[c] = -INFINITY;
        }
    }

    float m = fmaxf(fmaxf(sc[0], sc[1]), fmaxf(sc[2], sc[3]));
    #pragma unroll
    for (int off = 16; off >= 1; off >>= 1)
        m = fmaxf(m, __shfl_xor_sync(0xffffffffu, m, off));
    float p[4]; float sum = 0.f;
    #pragma unroll
    for (int c = 0; c < 4; c++) { p[c] = __expf(sc[c] - m); sum += p[c]; }
    #pragma unroll
    for (int off = 16; off >= 1; off >>= 1)
        sum += __shfl_xor_sync(0xffffffffu, sum, off);
    const float inv = 1.f / sum;
    #pragma unroll
    for (int c = 0; c < 4; c++) p[c] *= inv;

    float o0 = 0.f, o1 = 0.f;
    #pragma unroll 4
    for (int l = 0; l < WIN; l++) {
        float w = __shfl_sync(0xffffffffu, p[l >> 5], l & 31);
        const float* vrow = Vs + (wr + l) * HD;
        o0 = fmaf(w, vrow[lane],      o0);
        o1 = fmaf(w, vrow[lane + 32], o1);
    }
    float* orow = O + ((size_t)(b * Tv + qi)) * Dm + h * HD;
    orow[lane]      = o0;
    orow[lane + 32] = o1;
}

// ---------------- launch ----------------------------------------------------
extern "C" void kernel_launch(void* const* d_in, const int* in_sizes, int n_in,
                              void* d_out, int out_size)
{
    const float* X  = (const float*)d_in[0];
    const float* Wq = (const float*)d_in[1];
    const float* Wk = (const float*)d_in[2];
    const float* Wv = (const float*)d_in[3];
    const float* W1 = (const float*)d_in[4];
    const float* W2 = (const float*)d_in[5];
    float* out = (float*)d_out;

    __half *Xhi,*Xlo,*Wqkv,*W1h,*W2h,*AOhi,*AOlo,*H1hi,*H1lo;
    float *QKVlin,*Qh,*Kh,*Vh,*AO;
    cudaGetSymbolAddress((void**)&Xhi, g_Xhi);   cudaGetSymbolAddress((void**)&Xlo, g_Xlo);
    cudaGetSymbolAddress((void**)&Wqkv, g_Wqkv);
    cudaGetSymbolAddress((void**)&W1h, g_W1);    cudaGetSymbolAddress((void**)&W2h, g_W2);
    cudaGetSymbolAddress((void**)&AOhi, g_AOhi); cudaGetSymbolAddress((void**)&AOlo, g_AOlo);
    cudaGetSymbolAddress((void**)&H1hi, g_H1hi); cudaGetSymbolAddress((void**)&H1lo, g_H1lo);
    cudaGetSymbolAddress((void**)&QKVlin, g_QKVlin);
    cudaGetSymbolAddress((void**)&Qh, g_Q);      cudaGetSymbolAddress((void**)&Kh, g_K);
    cudaGetSymbolAddress((void**)&Vh, g_V);      cudaGetSymbolAddress((void**)&AO, g_AO);

    cudaFuncSetAttribute(mma_gemm<0>, cudaFuncAttributeMaxDynamicSharedMemorySize, GEMM_SMEM);
    cudaFuncSetAttribute(mma_gemm<1>, cudaFuncAttributeMaxDynamicSharedMemorySize, GEMM_SMEM);
    cudaFuncSetAttribute(attn_kernel, cudaFuncAttributeMaxDynamicSharedMemorySize, ATTN_SMEM);

    // 0) RoPE table (double-precision accurate, tiny)
    rope_table_kernel<<<(Tv*32 + 255)/256, 256>>>();

    // 1) operand conversions: A-side hi/lo fp16 split, B-side fp16
    split_kernel<<<(Mtok*Dm/4 + 255)/256, 256>>>(X, Xhi, Xlo, Mtok*Dm);
    cvt_kernel<<<(Dm*Dm/4 + 255)/256, 256>>>(Wq, Wqkv,             Dm*Dm);
    cvt_kernel<<<(NKV*HD*Dm/4 + 255)/256, 256>>>(Wk, Wqkv + 1024*Dm, NKV*HD*Dm);
    cvt_kernel<<<(NKV*HD*Dm/4 + 255)/256, 256>>>(Wv, Wqkv + 1280*Dm, NKV*HD*Dm);
    cvt_kernel<<<(DFF*Dm/4 + 255)/256, 256>>>(W1, W1h, DFF*Dm);
    cvt_kernel<<<(Dm*DFF/4 + 255)/256, 256>>>(W2, W2h, Dm*DFF);

    // 2) fused QKV projection: QKVlin = X @ Wqkv^T   (M=4096, N=1536, K=1024)
    mma_gemm<0><<<dim3(NQKV/GBN, Mtok/GBM), 256, GEMM_SMEM>>>(
        Xhi, Xlo, Wqkv, QKVlin, nullptr, nullptr, Mtok, NQKV, Dm);

    // 3) RoPE + head-major permute
    rope_apply_kernel<<<(Mtok*NH*32 + 255)/256, 256>>>(QKVlin, Qh, NH, 0,    1);
    rope_apply_kernel<<<(Mtok*NKV*32 + 255)/256, 256>>>(QKVlin, Kh, NKV, 1024, 1);
    rope_apply_kernel<<<(Mtok*NKV*32 + 255)/256, 256>>>(QKVlin, Vh, NKV, 1280, 0);

    // 4) sliding-window attention (fp32)
    attn_kernel<<<dim3(Tv/QB, NH, Bv), 256, ATTN_SMEM>>>(Qh, Kh, Vh, AO);

    // 5) split AO for MLP input
    split_kernel<<<(Mtok*Dm/4 + 255)/256, 256>>>(AO, AOhi, AOlo, Mtok*Dm);

    // 6) MLP1: H1 = silu(AO @ W1^T), written as fp16 hi/lo split
    mma_gemm<1><<<dim3(DFF/GBN, Mtok/GBM), 256, GEMM_SMEM>>>(
        AOhi, AOlo, W1h, nullptr, H1hi, H1lo, Mtok, DFF, Dm);

    // 7) MLP2: out = H1 @ W2^T (fp32)
    mma_gemm<0><<<dim3(Dm/GBN, Mtok/GBM), 256, GEMM_SMEM>>>(
        H1hi, H1lo, W2h, out, nullptr, nullptr, Mtok, Dm, DFF);
}